// round 1
// baseline (speedup 1.0000x reference)
#include <cuda_runtime.h>

// DempsterSchaferCombine — algebraically reduced.
//
// Reference per pixel (C = 21):
//   S1=sum(a1), S2=sum(a2), b=(a-1)/S, u=C/S,
//   K = sum(b1)sum(b2) - sum(b1*b2), denom = 1-K
//   b_a = (b1*b2 + b1*u2 + b2*u1)/denom, u_a = u1*u2/denom, S_a = C/u_a
//   out = b_a*S_a + 1
// Substituting e = a-1 and expanding, denom and S1,S2 cancel exactly:
//   out = e1*e2/C + e1 + e2 + 1 = (a1-1)*(a2-1)/C + a1 + a2 - 1
// => pure elementwise op, layout-independent (NCHW transpose is identity here).

#define INV_C (1.0f / 21.0f)

__global__ __launch_bounds__(256) void ds_combine_kernel(
    const float4* __restrict__ a1,
    const float4* __restrict__ a2,
    float4* __restrict__ out,
    int n4)
{
    int i = blockIdx.x * blockDim.x + threadIdx.x;
    if (i >= n4) return;

    float4 x = __ldg(a1 + i);
    float4 y = __ldg(a2 + i);

    float4 r;
    r.x = fmaf((x.x - 1.0f) * (y.x - 1.0f), INV_C, x.x + y.x - 1.0f);
    r.y = fmaf((x.y - 1.0f) * (y.y - 1.0f), INV_C, x.y + y.y - 1.0f);
    r.z = fmaf((x.z - 1.0f) * (y.z - 1.0f), INV_C, x.z + y.z - 1.0f);
    r.w = fmaf((x.w - 1.0f) * (y.w - 1.0f), INV_C, x.w + y.w - 1.0f);

    out[i] = r;
}

// Tail handler for element counts not divisible by 4 (not needed for this
// shape, 44,040,192 % 4 == 0, but kept for safety).
__global__ void ds_combine_tail(
    const float* __restrict__ a1,
    const float* __restrict__ a2,
    float* __restrict__ out,
    int start, int n)
{
    int i = start + blockIdx.x * blockDim.x + threadIdx.x;
    if (i >= n) return;
    float x = a1[i], y = a2[i];
    out[i] = fmaf((x - 1.0f) * (y - 1.0f), INV_C, x + y - 1.0f);
}

extern "C" void kernel_launch(void* const* d_in, const int* in_sizes, int n_in,
                              void* d_out, int out_size)
{
    const float* a1 = (const float*)d_in[0];
    const float* a2 = (const float*)d_in[1];
    float* out = (float*)d_out;

    int n = out_size;          // 8*21*512*512 = 44,040,192
    int n4 = n >> 2;

    const int threads = 256;
    int blocks = (n4 + threads - 1) / threads;
    ds_combine_kernel<<<blocks, threads>>>(
        (const float4*)a1, (const float4*)a2, (float4*)out, n4);

    int tail_start = n4 << 2;
    int tail = n - tail_start;
    if (tail > 0) {
        ds_combine_tail<<<1, 128>>>(a1, a2, out, tail_start, n);
    }
}